// round 1
// baseline (speedup 1.0000x reference)
#include <cuda_runtime.h>
#include <math.h>

#define Bn   2
#define Sn   4096
#define HIDn 1024
#define NHn  16
#define HDn  64
#define Wn   128
#define Mn   (Bn * Sn)          // 8192 rows
#define Kn   1024
#define NBLK (Sn / Wn)          // 32 query blocks
#define NEG_BIG (-3.402823466e38f)

// ---------------- scratch (device globals; no runtime allocation) ----------
__device__ float g_q[Bn * NHn * Sn * HDn];     // [B,H,S,D]
__device__ float g_k[Bn * NHn * Sn * HDn];
__device__ float g_v[Bn * NHn * Sn * HDn];
__device__ float g_ctx[Mn * HIDn];             // [B,S,H*D]

// ---------------- SGEMM: C[m,n] = sum_k A[m,k]*W[n,k] + bias[n] ------------
// A:[M,K] row-major, W:[N,K] row-major (both K-contiguous).
// mode 0/1/2: write to g_q/g_k/g_v in [B,H,S,D] layout.
// mode 3:     A is g_ctx, plain row-major write to Cplain ([M,1024]).
__global__ __launch_bounds__(256) void sgemm_nt(
    const float* __restrict__ A, const float* __restrict__ Wt,
    const float* __restrict__ bias, float* __restrict__ Cplain, int mode)
{
    __shared__ float As[16][132];
    __shared__ float Bs[16][132];

    const int tid = threadIdx.x;
    const int tx = tid & 15;          // col group
    const int ty = tid >> 4;          // row group
    const int m0 = blockIdx.y * 128;
    const int n0 = blockIdx.x * 128;

    const float* Ap = (mode == 3) ? g_ctx : A;

    float acc[8][8];
#pragma unroll
    for (int i = 0; i < 8; ++i)
#pragma unroll
        for (int j = 0; j < 8; ++j) acc[i][j] = 0.f;

    for (int k0 = 0; k0 < Kn; k0 += 16) {
        // cooperative load: 128 rows x 16 cols each for A and W, transposed into smem
#pragma unroll
        for (int li = tid; li < 512; li += 256) {
            int r  = li >> 2;
            int kc = (li & 3) * 4;
            float4 av = *(const float4*)&Ap[(long)(m0 + r) * Kn + k0 + kc];
            As[kc + 0][r] = av.x; As[kc + 1][r] = av.y;
            As[kc + 2][r] = av.z; As[kc + 3][r] = av.w;
            float4 bv = *(const float4*)&Wt[(long)(n0 + r) * Kn + k0 + kc];
            Bs[kc + 0][r] = bv.x; Bs[kc + 1][r] = bv.y;
            Bs[kc + 2][r] = bv.z; Bs[kc + 3][r] = bv.w;
        }
        __syncthreads();

#pragma unroll
        for (int kk = 0; kk < 16; ++kk) {
            float a[8], b[8];
            float4 a0 = *(const float4*)&As[kk][ty * 8];
            float4 a1 = *(const float4*)&As[kk][ty * 8 + 4];
            float4 b0 = *(const float4*)&Bs[kk][tx * 8];
            float4 b1 = *(const float4*)&Bs[kk][tx * 8 + 4];
            a[0]=a0.x; a[1]=a0.y; a[2]=a0.z; a[3]=a0.w;
            a[4]=a1.x; a[5]=a1.y; a[6]=a1.z; a[7]=a1.w;
            b[0]=b0.x; b[1]=b0.y; b[2]=b0.z; b[3]=b0.w;
            b[4]=b1.x; b[5]=b1.y; b[6]=b1.z; b[7]=b1.w;
#pragma unroll
            for (int i = 0; i < 8; ++i)
#pragma unroll
                for (int j = 0; j < 8; ++j)
                    acc[i][j] += a[i] * b[j];
        }
        __syncthreads();
    }

    // epilogue
#pragma unroll
    for (int i = 0; i < 8; ++i) {
        int mg = m0 + ty * 8 + i;
#pragma unroll
        for (int jv = 0; jv < 2; ++jv) {
            int ng = n0 + tx * 8 + jv * 4;
            float4 r;
            r.x = acc[i][jv * 4 + 0] + bias[ng + 0];
            r.y = acc[i][jv * 4 + 1] + bias[ng + 1];
            r.z = acc[i][jv * 4 + 2] + bias[ng + 2];
            r.w = acc[i][jv * 4 + 3] + bias[ng + 3];
            float* dst;
            if (mode <= 2) {
                int bb = mg >> 12, ss = mg & 4095;
                int hh = ng >> 6,  dd = ng & 63;
                float* base = (mode == 0) ? g_q : (mode == 1) ? g_k : g_v;
                dst = base + ((((long)bb * NHn + hh) * Sn) + ss) * HDn + dd;
            } else {
                dst = Cplain + (long)mg * HIDn + ng;
            }
            *(float4*)dst = r;
        }
    }
}

// ---------------- RoPE (in place on g_q, g_k) ------------------------------
__global__ void rope_kernel()
{
    int t   = blockIdx.x * blockDim.x + threadIdx.x;   // over B*NH*S*32
    int i   = t & 31;
    int row = t >> 5;                                  // row in [B*NH*S)
    int s   = row & (Sn - 1);

    // inv_freq[i] = 10000^{-i/32}; compute in double, round once.
    double e = -(double)i * (9.210340371976184 / 32.0); // ln(10000)
    float inv = (float)exp(e);
    float ang = (float)s * inv;
    float si, co;
    sincosf(ang, &si, &co);

    long base = (long)row * HDn;
    float x1 = g_q[base + i], x2 = g_q[base + i + 32];
    g_q[base + i]      = x1 * co - x2 * si;
    g_q[base + i + 32] = x2 * co + x1 * si;
    float y1 = g_k[base + i], y2 = g_k[base + i + 32];
    g_k[base + i]      = y1 * co - y2 * si;
    g_k[base + i + 32] = y2 * co + y1 * si;
}

// ---------------- banded attention -----------------------------------------
// grid (NBLK, NH, B), 128 threads: thread = one query row of the block.
// Keys: 2W window [(n-1)W, (n+1)W), band mask qi <= kj <= qi+W (local coords).
__global__ __launch_bounds__(128) void attn_kernel()
{
    __shared__ float smem_pool[8192];   // 32 KB: [0:4096) K chunk, [4096:8192) V chunk

    const int n  = blockIdx.x;
    const int h  = blockIdx.y;
    const int b  = blockIdx.z;
    const int qi = threadIdx.x;          // 0..127
    const int tid = threadIdx.x;

    const long headbase = ((long)(b * NHn + h)) * Sn;   // row index base into [B*H*S]

    // stage q block (coalesced) then per-thread row into registers
    const float* qbase = g_q + (headbase + (long)n * Wn) * HDn;
    for (int i = tid; i < 2048; i += 128)
        ((float4*)smem_pool)[i] = ((const float4*)qbase)[i];
    __syncthreads();
    float rq[64];
#pragma unroll
    for (int d = 0; d < 64; ++d) rq[d] = smem_pool[qi * 64 + d];

    float m = NEG_BIG, l = 0.f;
    float acc[64];
#pragma unroll
    for (int d = 0; d < 64; ++d) acc[d] = 0.f;

    const int first_chunk = (n == 0) ? 2 : 0;   // n==0: only own block (kj>=W)

    for (int c = first_chunk; c < 4; ++c) {
        long krow0 = headbase + (long)((n - 1) * Wn + c * 64);
        const float* kb = g_k + krow0 * HDn;
        const float* vb = g_v + krow0 * HDn;
        __syncthreads();
        for (int i = tid; i < 1024; i += 128) {
            ((float4*)smem_pool)[i]        = ((const float4*)kb)[i];
            ((float4*)smem_pool)[1024 + i] = ((const float4*)vb)[i];
        }
        __syncthreads();

        for (int jt = 0; jt < 4; ++jt) {        // 16-key sub-chunks
            const int kj0 = c * 64 + jt * 16;
            float sc[16];
            float mx = NEG_BIG;
#pragma unroll
            for (int j = 0; j < 16; ++j) {
                int kj = kj0 + j;
                bool valid = (kj >= qi) && (kj <= qi + Wn);
                float s_ = NEG_BIG;
                if (valid) {
                    const float* kr = &smem_pool[(kj - c * 64) * 64];
                    float dot = 0.f;
#pragma unroll
                    for (int d = 0; d < 64; d += 4) {
                        float4 kv = *(const float4*)&kr[d];
                        dot += rq[d] * kv.x + rq[d+1] * kv.y
                             + rq[d+2] * kv.z + rq[d+3] * kv.w;
                    }
                    s_ = dot * 0.125f;          // 1/sqrt(64)
                }
                sc[j] = s_;
                mx = fmaxf(mx, s_);
            }
            float newm = fmaxf(m, mx);
            if (newm > NEG_BIG) {
                float f = expf(m - newm);       // m==NEG_BIG -> underflow to 0
                l *= f;
#pragma unroll
                for (int d = 0; d < 64; ++d) acc[d] *= f;
#pragma unroll
                for (int j = 0; j < 16; ++j) {
                    if (sc[j] > NEG_BIG) {
                        float p = expf(sc[j] - newm);
                        l += p;
                        const float* vr = &smem_pool[4096 + (kj0 + j - c * 64) * 64];
#pragma unroll
                        for (int d = 0; d < 64; d += 4) {
                            float4 vv = *(const float4*)&vr[d];
                            acc[d]   += p * vv.x; acc[d+1] += p * vv.y;
                            acc[d+2] += p * vv.z; acc[d+3] += p * vv.w;
                        }
                    }
                }
                m = newm;
            }
        }
    }

    // normalize + stage to smem, then coalesced write into [B,S,H*D]
    __syncthreads();
    float invl = 1.f / l;
#pragma unroll
    for (int d = 0; d < 64; ++d) smem_pool[qi * 64 + d] = acc[d] * invl;
    __syncthreads();

    float* obase = g_ctx + ((long)b * Sn + (long)n * Wn) * HIDn + h * HDn;
    for (int i = tid; i < 2048; i += 128) {
        int r  = i >> 4;          // row within block (16 float4 per row)
        int dq = i & 15;
        ((float4*)(obase + (long)r * HIDn))[dq] = ((const float4*)smem_pool)[i];
    }
}

// ---------------- launch ----------------------------------------------------
extern "C" void kernel_launch(void* const* d_in, const int* in_sizes, int n_in,
                              void* d_out, int out_size)
{
    const float* X  = (const float*)d_in[0];
    const float* Wq = (const float*)d_in[1];
    const float* bq = (const float*)d_in[2];
    const float* Wk = (const float*)d_in[3];
    const float* bk = (const float*)d_in[4];
    const float* Wv = (const float*)d_in[5];
    const float* bv = (const float*)d_in[6];
    const float* Wo = (const float*)d_in[7];
    const float* bo = (const float*)d_in[8];
    float* out = (float*)d_out;

    dim3 gg(HIDn / 128, Mn / 128);   // (8, 64)
    dim3 gt(256);

    sgemm_nt<<<gg, gt>>>(X, Wq, bq, nullptr, 0);
    sgemm_nt<<<gg, gt>>>(X, Wk, bk, nullptr, 1);
    sgemm_nt<<<gg, gt>>>(X, Wv, bv, nullptr, 2);

    int rope_threads = Bn * NHn * Sn * 32;
    rope_kernel<<<rope_threads / 256, 256>>>();

    dim3 ag(NBLK, NHn, Bn);
    attn_kernel<<<ag, 128>>>();

    sgemm_nt<<<gg, gt>>>(nullptr, Wo, bo, out, 3);
}

// round 10
// speedup vs baseline: 1.9803x; 1.9803x over previous
#include <cuda_runtime.h>
#include <cuda_bf16.h>
#include <math.h>
#include <stdint.h>

#define Bn   2
#define Sn   4096
#define HIDn 1024
#define NHn  16
#define HDn  64
#define Wn   128
#define Mn   (Bn * Sn)          // 8192 rows
#define Kn   1024
#define NBLK (Sn / Wn)          // 32 query blocks
#define NEG_BIG (-3.402823466e38f)

// GEMM tile config: static-smem mma.sync, fp32->bf16 split done in-kernel
#define BM 128
#define BN 128
#define KC 16                    // K elements per stage (one k16 step)
#define NCH (Kn / KC)            // 64 stages
#define RSB 48                   // padded row stride in BYTES (32B data + 16B pad)
#define SEC_BYTES (128 * RSB)    // 6144 per tensor section
#define STAGE_BYTES (4 * SEC_BYTES)   // Ah|Al|Wh|Wl = 24576
#define SMEM_TOTAL (2 * STAGE_BYTES)  // 49152 = 48KB static

// ---------------- scratch: EXACTLY R1's proven 128MiB static set ------------
__device__ float g_q[Bn * NHn * Sn * HDn];
__device__ float g_k[Bn * NHn * Sn * HDn];
__device__ float g_v[Bn * NHn * Sn * HDn];
__device__ float g_ctx[Mn * HIDn];

// ---------------- macros: asm expanded directly at the use site -------------
#define LDSM4(d0, d1, d2, d3, ad)                                              \
    asm volatile("ldmatrix.sync.aligned.m8n8.x4.shared.b16 {%0,%1,%2,%3}, [%4];" \
                 : "=r"(d0), "=r"(d1), "=r"(d2), "=r"(d3) : "r"(ad))

#define MMA16816(c0, c1, c2, c3, a0, a1, a2, a3, b0, b1)                       \
    asm volatile("mma.sync.aligned.m16n8k16.row.col.f32.bf16.bf16.f32 "        \
                 "{%0,%1,%2,%3}, {%4,%5,%6,%7}, {%8,%9}, {%0,%1,%2,%3};"        \
                 : "+f"(c0), "+f"(c1), "+f"(c2), "+f"(c3)                       \
                 : "r"(a0), "r"(a1), "r"(a2), "r"(a3), "r"(b0), "r"(b1))

// split one float4 into packed bf16 hi / lo pairs (register-only)
#define CVT_SPLIT(v, h01, h23, l01, l23)                                       \
    do {                                                                       \
        asm("cvt.rn.bf16x2.f32 %0, %1, %2;" : "=r"(h01) : "f"((v).y), "f"((v).x)); \
        asm("cvt.rn.bf16x2.f32 %0, %1, %2;" : "=r"(h23) : "f"((v).w), "f"((v).z)); \
        float r0_ = (v).x - __uint_as_float((h01) << 16);                      \
        float r1_ = (v).y - __uint_as_float((h01) & 0xFFFF0000u);              \
        float r2_ = (v).z - __uint_as_float((h23) << 16);                      \
        float r3_ = (v).w - __uint_as_float((h23) & 0xFFFF0000u);              \
        asm("cvt.rn.bf16x2.f32 %0, %1, %2;" : "=r"(l01) : "f"(r1_), "f"(r0_)); \
        asm("cvt.rn.bf16x2.f32 %0, %1, %2;" : "=r"(l23) : "f"(r3_), "f"(r2_)); \
    } while (0)

// convert+store one staged float4 to hi section (so) and lo section (+SEC)
#define SPLIT_STORE(v, sbase, so)                                              \
    do {                                                                       \
        uint32_t h01_, h23_, l01_, l23_;                                       \
        CVT_SPLIT(v, h01_, h23_, l01_, l23_);                                  \
        asm volatile("st.shared.v2.b32 [%0], {%1,%2};"                         \
                     :: "r"((sbase) + (so)), "r"(h01_), "r"(h23_) : "memory"); \
        asm volatile("st.shared.v2.b32 [%0], {%1,%2};"                         \
                     :: "r"((sbase) + (so) + SEC_BYTES), "r"(l01_), "r"(l23_)  \
                     : "memory");                                              \
    } while (0)

// ---------------- tensor-core GEMM via mma.sync, 48KB STATIC smem -----------
// C[m,n] = sum_k A[m,k]*W[n,k] + bias[n], 3-term bf16 split (Ah*Wh+Al*Wh+Ah*Wl)
// computed from fp32 operands with in-register conversion. 256 threads, 8
// warps (2x4), warp tile 64x32. Static memory footprint: ZERO extra arrays.
__global__ void __launch_bounds__(256) gemm_mma(const float* __restrict__ A,
                                                const float* __restrict__ Wt,
                                                const float* __restrict__ bias,
                                                float* __restrict__ outp, int mode)
{
    __shared__ __align__(1024) char smem_buf[SMEM_TOTAL];
    const uint32_t smb = (uint32_t)__cvta_generic_to_shared(smem_buf);

    const int tid  = threadIdx.x;
    const int lane = tid & 31;
    const int wid  = tid >> 5;
    const int wm   = (wid >> 2) * 64;      // warp m offset (0 or 64)
    const int wn   = (wid & 3) * 32;       // warp n offset
    const int n0   = blockIdx.x * BN;
    const int m0   = blockIdx.y * BM;

    const float* Asrc = (mode == 3) ? g_ctx : A;

    // per-thread load slots: r0 = tid>>2 (row), cq = tid&3 (16B chunk in row)
    const int r0 = tid >> 2;
    const int cq = tid & 3;
    const float* gp0 = Asrc + (size_t)(m0 + r0) * Kn + cq * 4;        // A rows 0-63
    const float* gp1 = Asrc + (size_t)(m0 + r0 + 64) * Kn + cq * 4;   // A rows 64-127
    const float* gp2 = Wt   + (size_t)(n0 + r0) * Kn + cq * 4;        // W rows 0-63
    const float* gp3 = Wt   + (size_t)(n0 + r0 + 64) * Kn + cq * 4;   // W rows 64-127
    const uint32_t so0 = (uint32_t)(r0 * RSB + cq * 8);
    const uint32_t so1 = (uint32_t)((r0 + 64) * RSB + cq * 8);
    const uint32_t so2 = 2u * SEC_BYTES + (uint32_t)(r0 * RSB + cq * 8);
    const uint32_t so3 = 2u * SEC_BYTES + (uint32_t)((r0 + 64) * RSB + cq * 8);

    float acc[4][4][4];
#pragma unroll
    for (int a = 0; a < 4; ++a)
#pragma unroll
        for (int b = 0; b < 4; ++b)
#pragma unroll
            for (int c = 0; c < 4; ++c) acc[a][b][c] = 0.f;

    // prologue: stage 0 -> buf0
    float4 rv0 = *(const float4*)gp0;
    float4 rv1 = *(const float4*)gp1;
    float4 rv2 = *(const float4*)gp2;
    float4 rv3 = *(const float4*)gp3;
    SPLIT_STORE(rv0, smb, so0);
    SPLIT_STORE(rv1, smb, so1);
    SPLIT_STORE(rv2, smb, so2);
    SPLIT_STORE(rv3, smb, so3);

    const uint32_t a_roff = (uint32_t)(wm + (lane & 15)) * RSB
                          + (uint32_t)((lane >> 4) * 16);
    const uint32_t b_roff = 2u * SEC_BYTES
                          + (uint32_t)(wn + (lane & 7) + ((lane >> 4) << 3)) * RSB
                          + (uint32_t)(((lane >> 3) & 1) * 16);

    for (int ch = 0; ch < NCH; ++ch) {
        const uint32_t sb  = smb + (uint32_t)(ch & 1) * STAGE_BYTES;
        const uint32_t sb2 = smb + (uint32_t)((ch & 1) ^ 1) * STAGE_BYTES;
        __syncthreads();                     // buf[ch&1] stores visible

        if (ch + 1 < NCH) {                  // issue next-stage global loads
            const int k0 = (ch + 1) * KC;
            rv0 = *(const float4*)(gp0 + k0);
            rv1 = *(const float4*)(gp1 + k0);
            rv2 = *(const float4*)(gp2 + k0);
            rv3 = *(const float4*)(gp3 + k0);
        }

        uint32_t ah[4][4], al[4][4];
#pragma unroll
        for (int mt = 0; mt < 4; ++mt) {
            uint32_t ad = sb + a_roff + (uint32_t)(mt * 16) * RSB;
            LDSM4(ah[mt][0], ah[mt][1], ah[mt][2], ah[mt][3], ad);
            LDSM4(al[mt][0], al[mt][1], al[mt][2], al[mt][3], ad + SEC_BYTES);
        }
#pragma unroll
        for (int p = 0; p < 2; ++p) {
            uint32_t bh[4], bl[4];
            uint32_t bd = sb + b_roff + (uint32_t)(p * 16) * RSB;
            LDSM4(bh[0], bh[1], bh[2], bh[3], bd);
            LDSM4(bl[0], bl[1], bl[2], bl[3], bd + SEC_BYTES);
#pragma unroll
            for (int mt = 0; mt < 4; ++mt) {
#pragma unroll
                for (int q = 0; q < 2; ++q) {
                    const int nt = p * 2 + q;
                    MMA16816(acc[mt][nt][0], acc[mt][nt][1],
                             acc[mt][nt][2], acc[mt][nt][3],
                             ah[mt][0], ah[mt][1], ah[mt][2], ah[mt][3],
                             bh[2*q], bh[2*q+1]);
                    MMA16816(acc[mt][nt][0], acc[mt][nt][1],
                             acc[mt][nt][2], acc[mt][nt][3],
                             al[mt][0], al[mt][1], al[mt][2], al[mt][3],
                             bh[2*q], bh[2*q+1]);
                    MMA16816(acc[mt][nt][0], acc[mt][nt][1],
                             acc[mt][nt][2], acc[mt][nt][3],
                             ah[mt][0], ah[mt][1], ah[mt][2], ah[mt][3],
                             bl[2*q], bl[2*q+1]);
                }
            }
        }

        if (ch + 1 < NCH) {                  // convert + store into other buffer
            SPLIT_STORE(rv0, sb2, so0);
            SPLIT_STORE(rv1, sb2, so1);
            SPLIT_STORE(rv2, sb2, so2);
            SPLIT_STORE(rv3, sb2, so3);
        }
    }

    // ---- epilogue: scatter c-fragments with bias ----------------------------
    float* qkv = (mode == 0) ? g_q : (mode == 1) ? g_k : g_v;
#pragma unroll
    for (int mt = 0; mt < 4; ++mt) {
#pragma unroll
        for (int nt = 0; nt < 4; ++nt) {
            const int gn = n0 + wn + nt * 8 + (lane & 3) * 2;
            const float b0 = bias[gn], b1 = bias[gn + 1];
#pragma unroll
            for (int h2 = 0; h2 < 2; ++h2) {
                const int gm = m0 + wm + mt * 16 + h2 * 8 + (lane >> 2);
                float2 v;
                v.x = acc[mt][nt][h2 * 2 + 0] + b0;
                v.y = acc[mt][nt][h2 * 2 + 1] + b1;
                if (mode <= 2) {
                    int bb = gm >> 12, ss = gm & 4095;
                    int hh = gn >> 6,  dd = gn & 63;
                    *(float2*)&qkv[((((size_t)bb * NHn + hh) * Sn) + ss) * HDn + dd] = v;
                } else {
                    *(float2*)&outp[(size_t)gm * HIDn + gn] = v;
                }
            }
        }
    }
}

// ---------------- RoPE (in place on g_q, g_k) ------------------------------
__global__ void rope_kernel()
{
    int t   = blockIdx.x * blockDim.x + threadIdx.x;
    int i   = t & 31;
    int row = t >> 5;
    int s   = row & (Sn - 1);

    double e = -(double)i * (9.210340371976184 / 32.0);
    float inv = (float)exp(e);
    float ang = (float)s * inv;
    float si, co;
    sincosf(ang, &si, &co);

    long base = (long)row * HDn;
    float x1 = g_q[base + i], x2 = g_q[base + i + 32];
    g_q[base + i]      = x1 * co - x2 * si;
    g_q[base + i + 32] = x2 * co + x1 * si;
    float y1 = g_k[base + i], y2 = g_k[base + i + 32];
    g_k[base + i]      = y1 * co - y2 * si;
    g_k[base + i + 32] = y2 * co + y1 * si;
}

// ---------------- banded attention -----------------------------------------
__global__ __launch_bounds__(128) void attn_kernel()
{
    __shared__ float smem_pool[8192];

    const int n  = blockIdx.x;
    const int h  = blockIdx.y;
    const int b  = blockIdx.z;
    const int qi = threadIdx.x;
    const int tid = threadIdx.x;

    const long headbase = ((long)(b * NHn + h)) * Sn;

    const float* qbase = g_q + (headbase + (long)n * Wn) * HDn;
    for (int i = tid; i < 2048; i += 128)
        ((float4*)smem_pool)[i] = ((const float4*)qbase)[i];
    __syncthreads();
    float rq[64];
#pragma unroll
    for (int d = 0; d < 64; ++d) rq[d] = smem_pool[qi * 64 + d];

    float m = NEG_BIG, l = 0.f;
    float acc[64];
#pragma unroll
    for (int d = 0; d < 64; ++d) acc[d] = 0.f;

    const int first_chunk = (n == 0) ? 2 : 0;

    for (int c = first_chunk; c < 4; ++c) {
        long krow0 = headbase + (long)((n - 1) * Wn + c * 64);
        const float* kb = g_k + krow0 * HDn;
        const float* vb = g_v + krow0 * HDn;
        __syncthreads();
        for (int i = tid; i < 1024; i += 128) {
            ((float4*)smem_pool)[i]        = ((const float4*)kb)[i];
            ((float4*)smem_pool)[1024 + i] = ((const float4*)vb)[i];
        }
        __syncthreads();

        for (int jt = 0; jt < 4; ++jt) {
            const int kj0 = c * 64 + jt * 16;
            float sc[16];
            float mx = NEG_BIG;
#pragma unroll
            for (int j = 0; j < 16; ++j) {
                int kj = kj0 + j;
                bool valid = (kj >= qi) && (kj <= qi + Wn);
                float s_ = NEG_BIG;
                if (valid) {
                    const float* kr = &smem_pool[(kj - c * 64) * 64];
                    float dot = 0.f;
#pragma unroll
                    for (int d = 0; d < 64; d += 4) {
                        float4 kv = *(const float4*)&kr[d];
                        dot += rq[d] * kv.x + rq[d+1] * kv.y
                             + rq[d+2] * kv.z + rq[d+3] * kv.w;
                    }
                    s_ = dot * 0.125f;
                }
                sc[j] = s_;
                mx = fmaxf(mx, s_);
            }
            float newm = fmaxf(m, mx);
            if (newm > NEG_BIG) {
                float f = expf(m - newm);
                l *= f;
#pragma unroll
                for (int d = 0; d < 64; ++d) acc[d] *= f;
#pragma unroll
                for (int j = 0; j < 16; ++j) {
                    if (sc[j] > NEG_BIG) {
                        float p = expf(sc[j] - newm);
                        l += p;
                        const float* vr = &smem_pool[4096 + (kj0 + j - c * 64) * 64];
#pragma unroll
                        for (int d = 0; d < 64; d += 4) {
                            float4 vv = *(const float4*)&vr[d];
                            acc[d]   += p * vv.x; acc[d+1] += p * vv.y;
                            acc[d+2] += p * vv.z; acc[d+3] += p * vv.w;
                        }
                    }
                }
                m = newm;
            }
        }
    }

    __syncthreads();
    float invl = 1.f / l;
#pragma unroll
    for (int d = 0; d < 64; ++d) smem_pool[qi * 64 + d] = acc[d] * invl;
    __syncthreads();

    float* obase = g_ctx + ((long)b * Sn + (long)n * Wn) * HIDn + h * HDn;
    for (int i = tid; i < 2048; i += 128) {
        int r  = i >> 4;
        int dq = i & 15;
        ((float4*)(obase + (long)r * HIDn))[dq] = ((const float4*)smem_pool)[i];
    }
}

// ---------------- launch ----------------------------------------------------
extern "C" void kernel_launch(void* const* d_in, const int* in_sizes, int n_in,
                              void* d_out, int out_size)
{
    const float* X  = (const float*)d_in[0];
    const float* Wq = (const float*)d_in[1];
    const float* bq = (const float*)d_in[2];
    const float* Wk = (const float*)d_in[3];
    const float* bk = (const float*)d_in[4];
    const float* Wv = (const float*)d_in[5];
    const float* bv = (const float*)d_in[6];
    const float* Wo = (const float*)d_in[7];
    const float* bo = (const float*)d_in[8];
    float* out = (float*)d_out;

    dim3 gg(HIDn / BN, Mn / BM);   // (8, 64)
    gemm_mma<<<gg, 256>>>(X, Wq, bq, nullptr, 0);
    gemm_mma<<<gg, 256>>>(X, Wk, bk, nullptr, 1);
    gemm_mma<<<gg, 256>>>(X, Wv, bv, nullptr, 2);

    rope_kernel<<<(Bn * NHn * Sn * 32) / 256, 256>>>();

    dim3 ag(NBLK, NHn, Bn);
    attn_kernel<<<ag, 128>>>();

    gemm_mma<<<gg, 256>>>(nullptr, Wo, bo, out, 3);
}